// round 7
// baseline (speedup 1.0000x reference)
#include <cuda_runtime.h>
#include <cuda_bf16.h>
#include <math.h>

#define N_NODES   65536
#define N_EDGES   1048576
#define IN_DIM    192
#define PE_DIM    64
#define HIDDEN    256
#define LATENT    128
#define NUM_G     64
#define N_PER     1024
#define K_PER     512
#define N_OUT     (NUM_G * K_PER)          // 32768
#define MAX_DEG   128

typedef unsigned long long u64;

// ---------------- packed f32x2 helpers (sm_103a FFMA2 pipe) ------------------
__device__ __forceinline__ u64 ffma2(u64 a, u64 b, u64 c) {
    u64 d;
    asm("fma.rn.f32x2 %0, %1, %2, %3;" : "=l"(d) : "l"(a), "l"(b), "l"(c));
    return d;
}
__device__ __forceinline__ u64 fadd2(u64 a, u64 b) {
    u64 d;
    asm("add.rn.f32x2 %0, %1, %2;" : "=l"(d) : "l"(a), "l"(b));
    return d;
}
__device__ __forceinline__ void unpack2(u64 v, float& lo, float& hi) {
    asm("mov.b64 {%0, %1}, %2;" : "=f"(lo), "=f"(hi) : "l"(v));
}

// ---------------- scratch (device globals; no allocation allowed) -----------
__device__ float g_buf0[N_NODES * 256];
__device__ float g_buf1[N_NODES * 256];
__device__ float g_z[N_NODES * LATENT];
__device__ float g_score[N_NODES];
__device__ float g_dinv[N_NODES];
__device__ int   g_cnt[N_NODES];
__device__ int   g_fill[N_NODES];
__device__ int   g_rowstart[N_NODES + 1];
__device__ int   g_colsrc[N_EDGES];
__device__ int   g_coledge[N_EDGES];
__device__ int   g_perm[N_OUT];
__device__ int   g_is64;

__device__ __forceinline__ int edge_at(const void* __restrict__ ei, int pos) {
    if (g_is64) return (int)((const long long*)ei)[pos];
    return ((const int*)ei)[pos];
}

// ---------------- CSR build ---------------------------------------------------
// zero + dtype detection (thread 0 of block 0)
__global__ void k_zero(const void* __restrict__ ei) {
    int i = blockIdx.x * blockDim.x + threadIdx.x;
    if (i < N_NODES) { g_cnt[i] = 0; g_fill[i] = 0; }
    if (i == 0) {
        const unsigned long long* p = (const unsigned long long*)ei;
        int is64 = 1;
        for (int j = 0; j < 64; j++)
            if (p[j] > 65535ull) { is64 = 0; break; }
        g_is64 = is64;
    }
}

__global__ void k_hist(const void* __restrict__ ei) {
    int e = blockIdx.x * blockDim.x + threadIdx.x;
    if (e < N_EDGES) atomicAdd(&g_cnt[edge_at(ei, N_EDGES + e)], 1);
}

// exclusive scan + dinv in one kernel
__global__ void k_scan() {
    __shared__ int sh[1024];
    int t = threadIdx.x;
    int base = t * 64;
    int s = 0;
    for (int j = 0; j < 64; j++) s += g_cnt[base + j];
    sh[t] = s;
    __syncthreads();
    int mine = s;
    for (int off = 1; off < 1024; off <<= 1) {
        int v = (t >= off) ? sh[t - off] : 0;
        __syncthreads();
        sh[t] += v;
        __syncthreads();
    }
    int run = sh[t] - mine;
    for (int j = 0; j < 64; j++) {
        int c = g_cnt[base + j];
        g_rowstart[base + j] = run;
        g_dinv[base + j] = (float)(1.0 / sqrt((double)(c + 1)));
        run += c;
    }
    if (t == 1023) g_rowstart[N_NODES] = sh[1023];
}

__global__ void k_scatter(const void* __restrict__ ei) {
    int e = blockIdx.x * blockDim.x + threadIdx.x;
    if (e < N_EDGES) {
        int s = edge_at(ei, e);
        int d = edge_at(ei, N_EDGES + e);
        int pos = g_rowstart[d] + atomicAdd(&g_fill[d], 1);
        g_colsrc[pos] = s;
        g_coledge[pos] = e;
    }
}

__global__ __launch_bounds__(256) void k_sortrows() {
    __shared__ int Es[8][MAX_DEG];
    __shared__ int Ss[8][MAX_DEG];
    int warp = (blockIdx.x * blockDim.x + threadIdx.x) >> 5;
    if (warp >= N_NODES) return;
    int lane = threadIdx.x & 31;
    int w = (threadIdx.x >> 5);
    int e0 = g_rowstart[warp], e1 = g_rowstart[warp + 1];
    int deg = e1 - e0;
    if (deg <= 1) return;
    if (deg > MAX_DEG) deg = MAX_DEG;
    for (int i = lane; i < deg; i += 32) {
        Es[w][i] = g_coledge[e0 + i];
        Ss[w][i] = g_colsrc[e0 + i];
    }
    __syncwarp();
    for (int i = lane; i < deg; i += 32) {
        int my_e = Es[w][i];
        int rank = 0;
        for (int j = 0; j < deg; j++) rank += (Es[w][j] < my_e);
        g_colsrc[e0 + rank] = Ss[w][i];
    }
}

// ---------------- GEMM (f32x2, pre-duplicated B, 128x128 tile) ---------------
// C[65536x256] = A[65536x256] @ B[256x256]; per-thread 8 rows (4 M-pairs) x 8 cols.
// Per output element: 16-deep IEEE-FMA k-tile chain, add.rn combine — bitwise
// identical to the prior rounds' accumulation sequence.
template <int MODE>
__global__ __launch_bounds__(256, 1) void k_gemm(
    const float* __restrict__ A0, const float* __restrict__ A1,
    const float* __restrict__ B0, const float* __restrict__ B1,
    float* __restrict__ C)
{
    __shared__ float As[2][16][130];
    __shared__ float Bs[2][16][256];   // each B value stored twice (lo,hi pair)
    int tid = threadIdx.x;
    int tx = tid & 15, ty = tid >> 4;
    int m0 = blockIdx.x * 128;
    int n0 = blockIdx.y * 128;
    const float* Bsel = (MODE == 0) ? B0 : (blockIdx.y == 0 ? B0 : B1);

    int arow0 = tid >> 2, aq0 = (tid & 3) * 4;
    int arow1 = arow0 + 64;
    int brow0 = tid >> 5, bq0 = (tid & 31) * 4;
    int brow1 = brow0 + 8;

    u64 acc[4][8];
    #pragma unroll
    for (int i = 0; i < 4; i++)
        #pragma unroll
        for (int j = 0; j < 8; j++) acc[i][j] = 0ull;

    float4 va0, va1, vb0, vb1;
    {   // tile 0 global loads
        if (MODE == 0) {
            va0 = (aq0 < IN_DIM) ? *(const float4*)&A0[(m0 + arow0) * IN_DIM + aq0]
                                 : *(const float4*)&A1[(m0 + arow0) * PE_DIM + (aq0 - IN_DIM)];
            va1 = (aq0 < IN_DIM) ? *(const float4*)&A0[(m0 + arow1) * IN_DIM + aq0]
                                 : *(const float4*)&A1[(m0 + arow1) * PE_DIM + (aq0 - IN_DIM)];
            vb0 = *(const float4*)&B0[brow0 * 256 + n0 + bq0];
            vb1 = *(const float4*)&B0[brow1 * 256 + n0 + bq0];
        } else {
            va0 = *(const float4*)&A0[(m0 + arow0) * 256 + aq0];
            va1 = *(const float4*)&A0[(m0 + arow1) * 256 + aq0];
            vb0 = *(const float4*)&Bsel[brow0 * 128 + bq0];
            vb1 = *(const float4*)&Bsel[brow1 * 128 + bq0];
        }
    }

    #pragma unroll 1
    for (int t = 0; t < 16; t++) {
        int cur = t & 1;
        As[cur][aq0 + 0][arow0] = va0.x; As[cur][aq0 + 1][arow0] = va0.y;
        As[cur][aq0 + 2][arow0] = va0.z; As[cur][aq0 + 3][arow0] = va0.w;
        As[cur][aq0 + 0][arow1] = va1.x; As[cur][aq0 + 1][arow1] = va1.y;
        As[cur][aq0 + 2][arow1] = va1.z; As[cur][aq0 + 3][arow1] = va1.w;
        // store B duplicated: (x,x,y,y) (z,z,w,w)
        *(float4*)&Bs[cur][brow0][bq0 * 2]     = make_float4(vb0.x, vb0.x, vb0.y, vb0.y);
        *(float4*)&Bs[cur][brow0][bq0 * 2 + 4] = make_float4(vb0.z, vb0.z, vb0.w, vb0.w);
        *(float4*)&Bs[cur][brow1][bq0 * 2]     = make_float4(vb1.x, vb1.x, vb1.y, vb1.y);
        *(float4*)&Bs[cur][brow1][bq0 * 2 + 4] = make_float4(vb1.z, vb1.z, vb1.w, vb1.w);
        __syncthreads();

        if (t < 15) {  // prefetch tile t+1
            int k0 = (t + 1) * 16;
            int col = k0 + aq0;
            if (MODE == 0) {
                va0 = (col < IN_DIM) ? *(const float4*)&A0[(m0 + arow0) * IN_DIM + col]
                                     : *(const float4*)&A1[(m0 + arow0) * PE_DIM + (col - IN_DIM)];
                va1 = (col < IN_DIM) ? *(const float4*)&A0[(m0 + arow1) * IN_DIM + col]
                                     : *(const float4*)&A1[(m0 + arow1) * PE_DIM + (col - IN_DIM)];
                vb0 = *(const float4*)&B0[(k0 + brow0) * 256 + n0 + bq0];
                vb1 = *(const float4*)&B0[(k0 + brow1) * 256 + n0 + bq0];
            } else {
                va0 = *(const float4*)&A0[(m0 + arow0) * 256 + col];
                va1 = *(const float4*)&A0[(m0 + arow1) * 256 + col];
                vb0 = *(const float4*)&Bsel[(k0 + brow0) * 128 + bq0];
                vb1 = *(const float4*)&Bsel[(k0 + brow1) * 128 + bq0];
            }
        }

        u64 accT[4][8];
        #pragma unroll
        for (int i = 0; i < 4; i++)
            #pragma unroll
            for (int j = 0; j < 8; j++) accT[i][j] = 0ull;

        #pragma unroll
        for (int k = 0; k < 16; k++) {
            u64 ap[4];
            #pragma unroll
            for (int i = 0; i < 4; i++)
                ap[i] = *(const u64*)&As[cur][k][ty * 8 + 2 * i];
            u64 bp[8];
            #pragma unroll
            for (int j = 0; j < 8; j++)
                bp[j] = *(const u64*)&Bs[cur][k][tx * 16 + 2 * j];
            #pragma unroll
            for (int i = 0; i < 4; i++)
                #pragma unroll
                for (int j = 0; j < 8; j++)
                    accT[i][j] = ffma2(ap[i], bp[j], accT[i][j]);
        }
        #pragma unroll
        for (int i = 0; i < 4; i++)
            #pragma unroll
            for (int j = 0; j < 8; j++)
                acc[i][j] = fadd2(acc[i][j], accT[i][j]);
        __syncthreads();
    }
    #pragma unroll
    for (int i = 0; i < 4; i++) {
        float lo[8], hi[8];
        #pragma unroll
        for (int j = 0; j < 8; j++) unpack2(acc[i][j], lo[j], hi[j]);
        int r0 = m0 + ty * 8 + 2 * i;
        *(float4*)&C[r0 * 256 + n0 + tx * 8]           = make_float4(lo[0], lo[1], lo[2], lo[3]);
        *(float4*)&C[r0 * 256 + n0 + tx * 8 + 4]       = make_float4(lo[4], lo[5], lo[6], lo[7]);
        *(float4*)&C[(r0 + 1) * 256 + n0 + tx * 8]     = make_float4(hi[0], hi[1], hi[2], hi[3]);
        *(float4*)&C[(r0 + 1) * 256 + n0 + tx * 8 + 4] = make_float4(hi[4], hi[5], hi[6], hi[7]);
    }
}

// ---------------- conv1 aggregation: 2 warps per node, 4-edge unroll ---------
__global__ __launch_bounds__(256) void k_agg(
    const float* __restrict__ in, float* __restrict__ out,
    const float* __restrict__ bias0, const float* __restrict__ bias1, int relu)
{
    int gw = (blockIdx.x * blockDim.x + threadIdx.x) >> 5;
    if (gw >= N_NODES * 2) return;
    int lane = threadIdx.x & 31;
    int d = gw >> 1;
    int half = gw & 1;
    const float4* in4 = (const float4*)in + half * 32;
    float dd = g_dinv[d];

    float a0 = 0.f, a1 = 0.f, a2 = 0.f, a3 = 0.f;
    int e0 = g_rowstart[d], e1 = g_rowstart[d + 1];
    int e = e0;
    for (; e + 3 < e1; e += 4) {
        int s0 = g_colsrc[e], s1 = g_colsrc[e + 1];
        int s2 = g_colsrc[e + 2], s3 = g_colsrc[e + 3];
        float n0 = __fmul_rn(g_dinv[s0], dd);
        float n1 = __fmul_rn(g_dinv[s1], dd);
        float n2 = __fmul_rn(g_dinv[s2], dd);
        float n3 = __fmul_rn(g_dinv[s3], dd);
        float4 b0 = in4[s0 * 64 + lane];
        float4 b1 = in4[s1 * 64 + lane];
        float4 b2 = in4[s2 * 64 + lane];
        float4 b3 = in4[s3 * 64 + lane];
        a0 = __fadd_rn(a0, __fmul_rn(n0, b0.x));
        a1 = __fadd_rn(a1, __fmul_rn(n0, b0.y));
        a2 = __fadd_rn(a2, __fmul_rn(n0, b0.z));
        a3 = __fadd_rn(a3, __fmul_rn(n0, b0.w));
        a0 = __fadd_rn(a0, __fmul_rn(n1, b1.x));
        a1 = __fadd_rn(a1, __fmul_rn(n1, b1.y));
        a2 = __fadd_rn(a2, __fmul_rn(n1, b1.z));
        a3 = __fadd_rn(a3, __fmul_rn(n1, b1.w));
        a0 = __fadd_rn(a0, __fmul_rn(n2, b2.x));
        a1 = __fadd_rn(a1, __fmul_rn(n2, b2.y));
        a2 = __fadd_rn(a2, __fmul_rn(n2, b2.z));
        a3 = __fadd_rn(a3, __fmul_rn(n2, b2.w));
        a0 = __fadd_rn(a0, __fmul_rn(n3, b3.x));
        a1 = __fadd_rn(a1, __fmul_rn(n3, b3.y));
        a2 = __fadd_rn(a2, __fmul_rn(n3, b3.z));
        a3 = __fadd_rn(a3, __fmul_rn(n3, b3.w));
    }
    for (; e < e1; e++) {
        int s0 = g_colsrc[e];
        float n0 = __fmul_rn(g_dinv[s0], dd);
        float4 b0 = in4[s0 * 64 + lane];
        a0 = __fadd_rn(a0, __fmul_rn(n0, b0.x));
        a1 = __fadd_rn(a1, __fmul_rn(n0, b0.y));
        a2 = __fadd_rn(a2, __fmul_rn(n0, b0.z));
        a3 = __fadd_rn(a3, __fmul_rn(n0, b0.w));
    }
    {
        float ns = __fmul_rn(dd, dd);
        float4 b = in4[d * 64 + lane];
        a0 = __fadd_rn(a0, __fmul_rn(ns, b.x));
        a1 = __fadd_rn(a1, __fmul_rn(ns, b.y));
        a2 = __fadd_rn(a2, __fmul_rn(ns, b.z));
        a3 = __fadd_rn(a3, __fmul_rn(ns, b.w));
    }
    const float* bias = half ? bias1 : bias0;
    int c = lane * 4;
    a0 = __fadd_rn(a0, bias[c + 0]);
    a1 = __fadd_rn(a1, bias[c + 1]);
    a2 = __fadd_rn(a2, bias[c + 2]);
    a3 = __fadd_rn(a3, bias[c + 3]);
    if (relu) {
        a0 = fmaxf(a0, 0.f); a1 = fmaxf(a1, 0.f);
        a2 = fmaxf(a2, 0.f); a3 = fmaxf(a3, 0.f);
    }
    ((float4*)out + half * 32)[d * 64 + lane] = make_float4(a0, a1, a2, a3);
}

// ---------------- fused conv2 aggregation + z + score ------------------------
// One warp per node: accumulate mu (features lane*4..) and lv in exact edge
// order, add bias, then z = mu + eps*expf(0.5*lv), score via double dot.
__global__ __launch_bounds__(256) void k_aggz(
    const float* __restrict__ in, float* __restrict__ outMuLv,
    const float* __restrict__ bmu, const float* __restrict__ blv,
    const float* __restrict__ eps, const float* __restrict__ w)
{
    int warp = (blockIdx.x * blockDim.x + threadIdx.x) >> 5;
    if (warp >= N_NODES) return;
    int lane = threadIdx.x & 31;
    int d = warp;
    float dd = g_dinv[d];
    const float4* in4 = (const float4*)in;

    float m0 = 0.f, m1 = 0.f, m2 = 0.f, m3 = 0.f;
    float v0 = 0.f, v1 = 0.f, v2 = 0.f, v3 = 0.f;
    int e0 = g_rowstart[d], e1 = g_rowstart[d + 1];
    int e = e0;
    for (; e + 1 < e1; e += 2) {
        int s0 = g_colsrc[e], s1 = g_colsrc[e + 1];
        float n0 = __fmul_rn(g_dinv[s0], dd);
        float n1 = __fmul_rn(g_dinv[s1], dd);
        float4 p0 = in4[s0 * 64 + lane];
        float4 q0 = in4[s0 * 64 + 32 + lane];
        float4 p1 = in4[s1 * 64 + lane];
        float4 q1 = in4[s1 * 64 + 32 + lane];
        m0 = __fadd_rn(m0, __fmul_rn(n0, p0.x));
        m1 = __fadd_rn(m1, __fmul_rn(n0, p0.y));
        m2 = __fadd_rn(m2, __fmul_rn(n0, p0.z));
        m3 = __fadd_rn(m3, __fmul_rn(n0, p0.w));
        v0 = __fadd_rn(v0, __fmul_rn(n0, q0.x));
        v1 = __fadd_rn(v1, __fmul_rn(n0, q0.y));
        v2 = __fadd_rn(v2, __fmul_rn(n0, q0.z));
        v3 = __fadd_rn(v3, __fmul_rn(n0, q0.w));
        m0 = __fadd_rn(m0, __fmul_rn(n1, p1.x));
        m1 = __fadd_rn(m1, __fmul_rn(n1, p1.y));
        m2 = __fadd_rn(m2, __fmul_rn(n1, p1.z));
        m3 = __fadd_rn(m3, __fmul_rn(n1, p1.w));
        v0 = __fadd_rn(v0, __fmul_rn(n1, q1.x));
        v1 = __fadd_rn(v1, __fmul_rn(n1, q1.y));
        v2 = __fadd_rn(v2, __fmul_rn(n1, q1.z));
        v3 = __fadd_rn(v3, __fmul_rn(n1, q1.w));
    }
    if (e < e1) {
        int s0 = g_colsrc[e];
        float n0 = __fmul_rn(g_dinv[s0], dd);
        float4 p0 = in4[s0 * 64 + lane];
        float4 q0 = in4[s0 * 64 + 32 + lane];
        m0 = __fadd_rn(m0, __fmul_rn(n0, p0.x));
        m1 = __fadd_rn(m1, __fmul_rn(n0, p0.y));
        m2 = __fadd_rn(m2, __fmul_rn(n0, p0.z));
        m3 = __fadd_rn(m3, __fmul_rn(n0, p0.w));
        v0 = __fadd_rn(v0, __fmul_rn(n0, q0.x));
        v1 = __fadd_rn(v1, __fmul_rn(n0, q0.y));
        v2 = __fadd_rn(v2, __fmul_rn(n0, q0.z));
        v3 = __fadd_rn(v3, __fmul_rn(n0, q0.w));
    }
    {   // self loop last
        float ns = __fmul_rn(dd, dd);
        float4 p = in4[d * 64 + lane];
        float4 q = in4[d * 64 + 32 + lane];
        m0 = __fadd_rn(m0, __fmul_rn(ns, p.x));
        m1 = __fadd_rn(m1, __fmul_rn(ns, p.y));
        m2 = __fadd_rn(m2, __fmul_rn(ns, p.z));
        m3 = __fadd_rn(m3, __fmul_rn(ns, p.w));
        v0 = __fadd_rn(v0, __fmul_rn(ns, q.x));
        v1 = __fadd_rn(v1, __fmul_rn(ns, q.y));
        v2 = __fadd_rn(v2, __fmul_rn(ns, q.z));
        v3 = __fadd_rn(v3, __fmul_rn(ns, q.w));
    }
    int c = lane * 4;
    m0 = __fadd_rn(m0, bmu[c + 0]); m1 = __fadd_rn(m1, bmu[c + 1]);
    m2 = __fadd_rn(m2, bmu[c + 2]); m3 = __fadd_rn(m3, bmu[c + 3]);
    v0 = __fadd_rn(v0, blv[c + 0]); v1 = __fadd_rn(v1, blv[c + 1]);
    v2 = __fadd_rn(v2, blv[c + 2]); v3 = __fadd_rn(v3, blv[c + 3]);

    float4 ep = ((const float4*)eps)[d * 32 + lane];
    float4 wv = ((const float4*)w)[lane];
    float4 z;
    z.x = __fadd_rn(m0, __fmul_rn(ep.x, expf(__fmul_rn(0.5f, v0))));
    z.y = __fadd_rn(m1, __fmul_rn(ep.y, expf(__fmul_rn(0.5f, v1))));
    z.z = __fadd_rn(m2, __fmul_rn(ep.z, expf(__fmul_rn(0.5f, v2))));
    z.w = __fadd_rn(m3, __fmul_rn(ep.w, expf(__fmul_rn(0.5f, v3))));
    double dot = (double)z.x * wv.x + (double)z.y * wv.y
               + (double)z.z * wv.z + (double)z.w * wv.w;
    double wsq = (double)wv.x * wv.x + (double)wv.y * wv.y
               + (double)wv.z * wv.z + (double)wv.w * wv.w;
    #pragma unroll
    for (int o = 16; o > 0; o >>= 1) {
        dot += __shfl_xor_sync(0xffffffffu, dot, o);
        wsq += __shfl_xor_sync(0xffffffffu, wsq, o);
    }
    ((float4*)outMuLv)[d * 64 + lane]      = make_float4(m0, m1, m2, m3);
    ((float4*)outMuLv)[d * 64 + 32 + lane] = make_float4(v0, v1, v2, v3);
    ((float4*)g_z)[d * 32 + lane] = z;
    if (lane == 0) g_score[d] = (float)tanh(dot / sqrt(wsq));
}

// ---------------- per-graph top-k: bitonic sort of 1024 ----------------------
__device__ __forceinline__ bool later_than(float sa, int ia, float sb, int ib) {
    return (sa < sb) || (sa == sb && ia > ib);
}

__global__ __launch_bounds__(512) void k_topk() {
    __shared__ float ss[1024];
    __shared__ int   si[1024];
    int g = blockIdx.x;
    int t = threadIdx.x;
    int base = g * N_PER;
    ss[t] = g_score[base + t];             si[t] = t;
    ss[t + 512] = g_score[base + t + 512]; si[t + 512] = t + 512;
    __syncthreads();
    for (int k = 2; k <= 1024; k <<= 1) {
        for (int j = k >> 1; j > 0; j >>= 1) {
            for (int i = t; i < 1024; i += 512) {
                int l = i ^ j;
                if (l > i) {
                    bool up = ((i & k) == 0);
                    if (later_than(ss[i], si[i], ss[l], si[l]) == up) {
                        float ts = ss[i]; ss[i] = ss[l]; ss[l] = ts;
                        int ti = si[i]; si[i] = si[l]; si[l] = ti;
                    }
                }
            }
            __syncthreads();
        }
    }
    g_perm[g * K_PER + t] = base + si[t];
}

// ---------------- gather epilogue --------------------------------------------
__global__ __launch_bounds__(256) void k_output(float* __restrict__ out) {
    const int OFF_MU = N_OUT * LATENT;
    const int OFF_LV = 2 * N_OUT * LATENT;
    const int OFF_B  = 3 * N_OUT * LATENT;
    const int OFF_P  = OFF_B + N_OUT;
    int warp = (blockIdx.x * blockDim.x + threadIdx.x) >> 5;
    if (warp >= N_OUT) return;
    int lane = threadIdx.x & 31;
    int node = g_perm[warp];
    float sc = g_score[node];
    float4 z = ((const float4*)g_z)[node * 32 + lane];
    z.x = __fmul_rn(z.x, sc); z.y = __fmul_rn(z.y, sc);
    z.z = __fmul_rn(z.z, sc); z.w = __fmul_rn(z.w, sc);
    ((float4*)out)[warp * 32 + lane] = z;
    const float4* muv4 = (const float4*)g_buf1;
    ((float4*)(out + OFF_MU))[warp * 32 + lane] = muv4[node * 64 + lane];
    ((float4*)(out + OFF_LV))[warp * 32 + lane] = muv4[node * 64 + 32 + lane];
    if (lane == 0) {
        out[OFF_B + warp] = (float)(node >> 10);
        out[OFF_P + warp] = (float)node;
    }
}

// ---------------- launch ------------------------------------------------------
extern "C" void kernel_launch(void* const* d_in, const int* in_sizes, int n_in,
                              void* d_out, int out_size)
{
    const float* x_raw = (const float*)d_in[0];
    const float* pe    = (const float*)d_in[1];
    const void*  ei    = d_in[2];
    const float* eps   = (const float*)d_in[4];
    const float* W1    = (const float*)d_in[5];
    const float* b1    = (const float*)d_in[6];
    const float* Wmu   = (const float*)d_in[7];
    const float* bmu   = (const float*)d_in[8];
    const float* Wlv   = (const float*)d_in[9];
    const float* blv   = (const float*)d_in[10];
    const float* wpool = (const float*)d_in[11];
    float* out = (float*)d_out;

    float* buf0; cudaGetSymbolAddress((void**)&buf0, g_buf0);
    float* buf1; cudaGetSymbolAddress((void**)&buf1, g_buf1);

    static cudaStream_t s2 = 0;
    static cudaEvent_t evFork = 0, evJoin = 0;
    static int init_done = 0;
    if (!init_done) {
        init_done = 1;
        if (cudaStreamCreateWithFlags(&s2, cudaStreamNonBlocking) != cudaSuccess) s2 = 0;
        if (s2) {
            if (cudaEventCreateWithFlags(&evFork, cudaEventDisableTiming) != cudaSuccess ||
                cudaEventCreateWithFlags(&evJoin, cudaEventDisableTiming) != cudaSuccess)
                s2 = 0;
        }
    }

    dim3 gg(N_NODES / 128, 2);

    if (s2) {
        cudaEventRecord(evFork, 0);
        cudaStreamWaitEvent(s2, evFork, 0);
        k_zero<<<N_NODES / 256, 256, 0, s2>>>(ei);
        k_hist<<<N_EDGES / 256, 256, 0, s2>>>(ei);
        k_scan<<<1, 1024, 0, s2>>>();
        k_gemm<0><<<gg, 256>>>(x_raw, pe, W1, nullptr, buf0);   // main stream
        k_scatter<<<N_EDGES / 256, 256, 0, s2>>>(ei);
        k_sortrows<<<(N_NODES * 32) / 256, 256, 0, s2>>>();
        cudaEventRecord(evJoin, s2);
        cudaStreamWaitEvent(0, evJoin, 0);
    } else {
        k_zero<<<N_NODES / 256, 256>>>(ei);
        k_hist<<<N_EDGES / 256, 256>>>(ei);
        k_scan<<<1, 1024>>>();
        k_gemm<0><<<gg, 256>>>(x_raw, pe, W1, nullptr, buf0);
        k_scatter<<<N_EDGES / 256, 256>>>(ei);
        k_sortrows<<<(N_NODES * 32) / 256, 256>>>();
    }

    k_agg<<<(N_NODES * 64) / 256, 256>>>(buf0, buf1, b1, b1 + 128, 1);
    k_gemm<1><<<gg, 256>>>(buf1, nullptr, Wmu, Wlv, buf0);
    k_aggz<<<(N_NODES * 32) / 256, 256>>>(buf0, buf1, bmu, blv, eps, wpool);
    k_topk<<<NUM_G, 512>>>();
    k_output<<<(N_OUT * 32) / 256, 256>>>(out);
}

// round 9
// speedup vs baseline: 1.5986x; 1.5986x over previous
#include <cuda_runtime.h>
#include <cuda_bf16.h>
#include <math.h>

#define N_NODES   65536
#define N_EDGES   1048576
#define IN_DIM    192
#define PE_DIM    64
#define HIDDEN    256
#define LATENT    128
#define NUM_G     64
#define N_PER     1024
#define K_PER     512
#define N_OUT     (NUM_G * K_PER)          // 32768
#define MAX_DEG   128

typedef unsigned long long u64;

// ---------------- packed f32x2 helpers (sm_103a FFMA2 pipe) ------------------
__device__ __forceinline__ u64 ffma2(u64 a, u64 b, u64 c) {
    u64 d;
    asm("fma.rn.f32x2 %0, %1, %2, %3;" : "=l"(d) : "l"(a), "l"(b), "l"(c));
    return d;
}
__device__ __forceinline__ u64 fadd2(u64 a, u64 b) {
    u64 d;
    asm("add.rn.f32x2 %0, %1, %2;" : "=l"(d) : "l"(a), "l"(b));
    return d;
}
__device__ __forceinline__ u64 pack2(float lo, float hi) {
    u64 d;
    asm("mov.b64 %0, {%1, %2};" : "=l"(d) : "f"(lo), "f"(hi));
    return d;
}
__device__ __forceinline__ void unpack2(u64 v, float& lo, float& hi) {
    asm("mov.b64 {%0, %1}, %2;" : "=f"(lo), "=f"(hi) : "l"(v));
}

// ---------------- scratch (device globals; no allocation allowed) -----------
__device__ float g_buf0[N_NODES * 256];
__device__ float g_buf1[N_NODES * 256];
__device__ float g_z[N_NODES * LATENT];
__device__ float g_score[N_NODES];
__device__ float g_dinv[N_NODES];
__device__ int   g_cnt[N_NODES];
__device__ int   g_fill[N_NODES];
__device__ int   g_rowstart[N_NODES + 1];
__device__ int   g_colsrc[N_EDGES];
__device__ int   g_coledge[N_EDGES];
__device__ int   g_perm[N_OUT];
__device__ int   g_is64;

__device__ __forceinline__ int edge_at(const void* __restrict__ ei, int pos) {
    if (g_is64) return (int)((const long long*)ei)[pos];
    return ((const int*)ei)[pos];
}

// ---------------- CSR build ---------------------------------------------------
__global__ void k_zero(const void* __restrict__ ei) {
    int i = blockIdx.x * blockDim.x + threadIdx.x;
    if (i < N_NODES) { g_cnt[i] = 0; g_fill[i] = 0; }
    if (i == 0) {
        const unsigned long long* p = (const unsigned long long*)ei;
        int is64 = 1;
        for (int j = 0; j < 64; j++)
            if (p[j] > 65535ull) { is64 = 0; break; }
        g_is64 = is64;
    }
}

__global__ void k_hist(const void* __restrict__ ei) {
    int e = blockIdx.x * blockDim.x + threadIdx.x;
    if (e < N_EDGES) atomicAdd(&g_cnt[edge_at(ei, N_EDGES + e)], 1);
}

// exclusive scan + dinv
__global__ void k_scan() {
    __shared__ int sh[1024];
    int t = threadIdx.x;
    int base = t * 64;
    int s = 0;
    for (int j = 0; j < 64; j++) s += g_cnt[base + j];
    sh[t] = s;
    __syncthreads();
    int mine = s;
    for (int off = 1; off < 1024; off <<= 1) {
        int v = (t >= off) ? sh[t - off] : 0;
        __syncthreads();
        sh[t] += v;
        __syncthreads();
    }
    int run = sh[t] - mine;
    for (int j = 0; j < 64; j++) {
        int c = g_cnt[base + j];
        g_rowstart[base + j] = run;
        g_dinv[base + j] = (float)(1.0 / sqrt((double)(c + 1)));
        run += c;
    }
    if (t == 1023) g_rowstart[N_NODES] = sh[1023];
}

__global__ void k_scatter(const void* __restrict__ ei) {
    int e = blockIdx.x * blockDim.x + threadIdx.x;
    if (e < N_EDGES) {
        int s = edge_at(ei, e);
        int d = edge_at(ei, N_EDGES + e);
        int pos = g_rowstart[d] + atomicAdd(&g_fill[d], 1);
        g_colsrc[pos] = s;
        g_coledge[pos] = e;
    }
}

__global__ __launch_bounds__(256) void k_sortrows() {
    __shared__ int Es[8][MAX_DEG];
    __shared__ int Ss[8][MAX_DEG];
    int warp = (blockIdx.x * blockDim.x + threadIdx.x) >> 5;
    if (warp >= N_NODES) return;
    int lane = threadIdx.x & 31;
    int w = (threadIdx.x >> 5);
    int e0 = g_rowstart[warp], e1 = g_rowstart[warp + 1];
    int deg = e1 - e0;
    if (deg <= 1) return;
    if (deg > MAX_DEG) deg = MAX_DEG;
    for (int i = lane; i < deg; i += 32) {
        Es[w][i] = g_coledge[e0 + i];
        Ss[w][i] = g_colsrc[e0 + i];
    }
    __syncwarp();
    for (int i = lane; i < deg; i += 32) {
        int my_e = Es[w][i];
        int rank = 0;
        for (int j = 0; j < deg; j++) rank += (Es[w][j] < my_e);
        g_colsrc[e0 + rank] = Ss[w][i];
    }
}

// ---------------- GEMM (f32x2, double-buffered, 128x64 tile — R6 proven) -----
// Per output element: 16-deep IEEE-FMA k-tile chain, add.rn combine.
template <int MODE>
__global__ __launch_bounds__(256) void k_gemm(
    const float* __restrict__ A0, const float* __restrict__ A1,
    const float* __restrict__ B0, const float* __restrict__ B1,
    float* __restrict__ C)
{
    __shared__ float As[2][16][130];
    __shared__ float Bs[2][16][64];
    int tid = threadIdx.x;
    int tx = tid & 15, ty = tid >> 4;
    int m0 = blockIdx.x * 128;
    int n0 = blockIdx.y * 64;

    int arow0 = tid >> 2;                 // A: 2 float4 per thread
    int aq0   = (tid & 3) * 4;
    int arow1 = (tid + 256) >> 2;
    int aq1   = aq0;
    int brow  = tid >> 4;                 // B: 1 float4 per thread
    int bq    = (tid & 15) * 4;

    u64 acc[4][4];
    #pragma unroll
    for (int i = 0; i < 4; i++)
        #pragma unroll
        for (int j = 0; j < 4; j++) acc[i][j] = 0ull;

    float4 va0, va1, vb;
    {
        int col0 = aq0, col1 = aq1;
        if (MODE == 0) {
            va0 = (col0 < IN_DIM) ? *(const float4*)&A0[(m0 + arow0) * IN_DIM + col0]
                                  : *(const float4*)&A1[(m0 + arow0) * PE_DIM + (col0 - IN_DIM)];
            va1 = (col1 < IN_DIM) ? *(const float4*)&A0[(m0 + arow1) * IN_DIM + col1]
                                  : *(const float4*)&A1[(m0 + arow1) * PE_DIM + (col1 - IN_DIM)];
            vb  = *(const float4*)&B0[brow * 256 + n0 + bq];
        } else {
            va0 = *(const float4*)&A0[(m0 + arow0) * 256 + col0];
            va1 = *(const float4*)&A0[(m0 + arow1) * 256 + col1];
            int col = n0 + bq;
            vb = (col < 128) ? *(const float4*)&B0[brow * 128 + col]
                             : *(const float4*)&B1[brow * 128 + (col - 128)];
        }
    }

    #pragma unroll 1
    for (int t = 0; t < 16; t++) {
        int cur = t & 1;
        As[cur][aq0 + 0][arow0] = va0.x; As[cur][aq0 + 1][arow0] = va0.y;
        As[cur][aq0 + 2][arow0] = va0.z; As[cur][aq0 + 3][arow0] = va0.w;
        As[cur][aq1 + 0][arow1] = va1.x; As[cur][aq1 + 1][arow1] = va1.y;
        As[cur][aq1 + 2][arow1] = va1.z; As[cur][aq1 + 3][arow1] = va1.w;
        *(float4*)&Bs[cur][brow][bq] = vb;
        __syncthreads();

        if (t < 15) {
            int k0 = (t + 1) * 16;
            int col0 = k0 + aq0, col1 = k0 + aq1;
            if (MODE == 0) {
                va0 = (col0 < IN_DIM) ? *(const float4*)&A0[(m0 + arow0) * IN_DIM + col0]
                                      : *(const float4*)&A1[(m0 + arow0) * PE_DIM + (col0 - IN_DIM)];
                va1 = (col1 < IN_DIM) ? *(const float4*)&A0[(m0 + arow1) * IN_DIM + col1]
                                      : *(const float4*)&A1[(m0 + arow1) * PE_DIM + (col1 - IN_DIM)];
                vb  = *(const float4*)&B0[(k0 + brow) * 256 + n0 + bq];
            } else {
                va0 = *(const float4*)&A0[(m0 + arow0) * 256 + col0];
                va1 = *(const float4*)&A0[(m0 + arow1) * 256 + col1];
                int col = n0 + bq;
                vb = (col < 128) ? *(const float4*)&B0[(k0 + brow) * 128 + col]
                                 : *(const float4*)&B1[(k0 + brow) * 128 + (col - 128)];
            }
        }

        u64 accT[4][4];
        #pragma unroll
        for (int i = 0; i < 4; i++)
            #pragma unroll
            for (int j = 0; j < 4; j++) accT[i][j] = 0ull;

        #pragma unroll
        for (int k = 0; k < 16; k++) {
            u64 ap[4];
            #pragma unroll
            for (int i = 0; i < 4; i++)
                ap[i] = *(const u64*)&As[cur][k][ty * 8 + 2 * i];
            float4 bv = *(const float4*)&Bs[cur][k][tx * 4];
            u64 bp[4] = { pack2(bv.x, bv.x), pack2(bv.y, bv.y),
                          pack2(bv.z, bv.z), pack2(bv.w, bv.w) };
            #pragma unroll
            for (int i = 0; i < 4; i++)
                #pragma unroll
                for (int j = 0; j < 4; j++)
                    accT[i][j] = ffma2(ap[i], bp[j], accT[i][j]);
        }
        #pragma unroll
        for (int i = 0; i < 4; i++)
            #pragma unroll
            for (int j = 0; j < 4; j++)
                acc[i][j] = fadd2(acc[i][j], accT[i][j]);
        __syncthreads();
    }
    #pragma unroll
    for (int i = 0; i < 4; i++) {
        float lo[4], hi[4];
        #pragma unroll
        for (int j = 0; j < 4; j++) unpack2(acc[i][j], lo[j], hi[j]);
        int r0 = m0 + ty * 8 + 2 * i;
        *(float4*)&C[r0 * 256 + n0 + tx * 4]       = make_float4(lo[0], lo[1], lo[2], lo[3]);
        *(float4*)&C[(r0 + 1) * 256 + n0 + tx * 4] = make_float4(hi[0], hi[1], hi[2], hi[3]);
    }
}

// ---------------- conv1 aggregation: 2 warps per node, 4-edge unroll ---------
__global__ __launch_bounds__(256) void k_agg(
    const float* __restrict__ in, float* __restrict__ out,
    const float* __restrict__ bias0, const float* __restrict__ bias1, int relu)
{
    int gw = (blockIdx.x * blockDim.x + threadIdx.x) >> 5;
    if (gw >= N_NODES * 2) return;
    int lane = threadIdx.x & 31;
    int d = gw >> 1;
    int half = gw & 1;
    const float4* in4 = (const float4*)in + half * 32;
    float dd = g_dinv[d];

    float a0 = 0.f, a1 = 0.f, a2 = 0.f, a3 = 0.f;
    int e0 = g_rowstart[d], e1 = g_rowstart[d + 1];
    int e = e0;
    for (; e + 3 < e1; e += 4) {
        int s0 = g_colsrc[e], s1 = g_colsrc[e + 1];
        int s2 = g_colsrc[e + 2], s3 = g_colsrc[e + 3];
        float n0 = __fmul_rn(g_dinv[s0], dd);
        float n1 = __fmul_rn(g_dinv[s1], dd);
        float n2 = __fmul_rn(g_dinv[s2], dd);
        float n3 = __fmul_rn(g_dinv[s3], dd);
        float4 b0 = in4[s0 * 64 + lane];
        float4 b1 = in4[s1 * 64 + lane];
        float4 b2 = in4[s2 * 64 + lane];
        float4 b3 = in4[s3 * 64 + lane];
        a0 = __fadd_rn(a0, __fmul_rn(n0, b0.x));
        a1 = __fadd_rn(a1, __fmul_rn(n0, b0.y));
        a2 = __fadd_rn(a2, __fmul_rn(n0, b0.z));
        a3 = __fadd_rn(a3, __fmul_rn(n0, b0.w));
        a0 = __fadd_rn(a0, __fmul_rn(n1, b1.x));
        a1 = __fadd_rn(a1, __fmul_rn(n1, b1.y));
        a2 = __fadd_rn(a2, __fmul_rn(n1, b1.z));
        a3 = __fadd_rn(a3, __fmul_rn(n1, b1.w));
        a0 = __fadd_rn(a0, __fmul_rn(n2, b2.x));
        a1 = __fadd_rn(a1, __fmul_rn(n2, b2.y));
        a2 = __fadd_rn(a2, __fmul_rn(n2, b2.z));
        a3 = __fadd_rn(a3, __fmul_rn(n2, b2.w));
        a0 = __fadd_rn(a0, __fmul_rn(n3, b3.x));
        a1 = __fadd_rn(a1, __fmul_rn(n3, b3.y));
        a2 = __fadd_rn(a2, __fmul_rn(n3, b3.z));
        a3 = __fadd_rn(a3, __fmul_rn(n3, b3.w));
    }
    for (; e < e1; e++) {
        int s0 = g_colsrc[e];
        float n0 = __fmul_rn(g_dinv[s0], dd);
        float4 b0 = in4[s0 * 64 + lane];
        a0 = __fadd_rn(a0, __fmul_rn(n0, b0.x));
        a1 = __fadd_rn(a1, __fmul_rn(n0, b0.y));
        a2 = __fadd_rn(a2, __fmul_rn(n0, b0.z));
        a3 = __fadd_rn(a3, __fmul_rn(n0, b0.w));
    }
    {
        float ns = __fmul_rn(dd, dd);
        float4 b = in4[d * 64 + lane];
        a0 = __fadd_rn(a0, __fmul_rn(ns, b.x));
        a1 = __fadd_rn(a1, __fmul_rn(ns, b.y));
        a2 = __fadd_rn(a2, __fmul_rn(ns, b.z));
        a3 = __fadd_rn(a3, __fmul_rn(ns, b.w));
    }
    const float* bias = half ? bias1 : bias0;
    int c = lane * 4;
    a0 = __fadd_rn(a0, bias[c + 0]);
    a1 = __fadd_rn(a1, bias[c + 1]);
    a2 = __fadd_rn(a2, bias[c + 2]);
    a3 = __fadd_rn(a3, bias[c + 3]);
    if (relu) {
        a0 = fmaxf(a0, 0.f); a1 = fmaxf(a1, 0.f);
        a2 = fmaxf(a2, 0.f); a3 = fmaxf(a3, 0.f);
    }
    ((float4*)out + half * 32)[d * 64 + lane] = make_float4(a0, a1, a2, a3);
}

// ---------------- fused conv2 aggregation + z + score ------------------------
__global__ __launch_bounds__(256) void k_aggz(
    const float* __restrict__ in, float* __restrict__ outMuLv,
    const float* __restrict__ bmu, const float* __restrict__ blv,
    const float* __restrict__ eps, const float* __restrict__ w)
{
    int warp = (blockIdx.x * blockDim.x + threadIdx.x) >> 5;
    if (warp >= N_NODES) return;
    int lane = threadIdx.x & 31;
    int d = warp;
    float dd = g_dinv[d];
    const float4* in4 = (const float4*)in;

    float m0 = 0.f, m1 = 0.f, m2 = 0.f, m3 = 0.f;
    float v0 = 0.f, v1 = 0.f, v2 = 0.f, v3 = 0.f;
    int e0 = g_rowstart[d], e1 = g_rowstart[d + 1];
    int e = e0;
    for (; e + 1 < e1; e += 2) {
        int s0 = g_colsrc[e], s1 = g_colsrc[e + 1];
        float n0 = __fmul_rn(g_dinv[s0], dd);
        float n1 = __fmul_rn(g_dinv[s1], dd);
        float4 p0 = in4[s0 * 64 + lane];
        float4 q0 = in4[s0 * 64 + 32 + lane];
        float4 p1 = in4[s1 * 64 + lane];
        float4 q1 = in4[s1 * 64 + 32 + lane];
        m0 = __fadd_rn(m0, __fmul_rn(n0, p0.x));
        m1 = __fadd_rn(m1, __fmul_rn(n0, p0.y));
        m2 = __fadd_rn(m2, __fmul_rn(n0, p0.z));
        m3 = __fadd_rn(m3, __fmul_rn(n0, p0.w));
        v0 = __fadd_rn(v0, __fmul_rn(n0, q0.x));
        v1 = __fadd_rn(v1, __fmul_rn(n0, q0.y));
        v2 = __fadd_rn(v2, __fmul_rn(n0, q0.z));
        v3 = __fadd_rn(v3, __fmul_rn(n0, q0.w));
        m0 = __fadd_rn(m0, __fmul_rn(n1, p1.x));
        m1 = __fadd_rn(m1, __fmul_rn(n1, p1.y));
        m2 = __fadd_rn(m2, __fmul_rn(n1, p1.z));
        m3 = __fadd_rn(m3, __fmul_rn(n1, p1.w));
        v0 = __fadd_rn(v0, __fmul_rn(n1, q1.x));
        v1 = __fadd_rn(v1, __fmul_rn(n1, q1.y));
        v2 = __fadd_rn(v2, __fmul_rn(n1, q1.z));
        v3 = __fadd_rn(v3, __fmul_rn(n1, q1.w));
    }
    if (e < e1) {
        int s0 = g_colsrc[e];
        float n0 = __fmul_rn(g_dinv[s0], dd);
        float4 p0 = in4[s0 * 64 + lane];
        float4 q0 = in4[s0 * 64 + 32 + lane];
        m0 = __fadd_rn(m0, __fmul_rn(n0, p0.x));
        m1 = __fadd_rn(m1, __fmul_rn(n0, p0.y));
        m2 = __fadd_rn(m2, __fmul_rn(n0, p0.z));
        m3 = __fadd_rn(m3, __fmul_rn(n0, p0.w));
        v0 = __fadd_rn(v0, __fmul_rn(n0, q0.x));
        v1 = __fadd_rn(v1, __fmul_rn(n0, q0.y));
        v2 = __fadd_rn(v2, __fmul_rn(n0, q0.z));
        v3 = __fadd_rn(v3, __fmul_rn(n0, q0.w));
    }
    {
        float ns = __fmul_rn(dd, dd);
        float4 p = in4[d * 64 + lane];
        float4 q = in4[d * 64 + 32 + lane];
        m0 = __fadd_rn(m0, __fmul_rn(ns, p.x));
        m1 = __fadd_rn(m1, __fmul_rn(ns, p.y));
        m2 = __fadd_rn(m2, __fmul_rn(ns, p.z));
        m3 = __fadd_rn(m3, __fmul_rn(ns, p.w));
        v0 = __fadd_rn(v0, __fmul_rn(ns, q.x));
        v1 = __fadd_rn(v1, __fmul_rn(ns, q.y));
        v2 = __fadd_rn(v2, __fmul_rn(ns, q.z));
        v3 = __fadd_rn(v3, __fmul_rn(ns, q.w));
    }
    int c = lane * 4;
    m0 = __fadd_rn(m0, bmu[c + 0]); m1 = __fadd_rn(m1, bmu[c + 1]);
    m2 = __fadd_rn(m2, bmu[c + 2]); m3 = __fadd_rn(m3, bmu[c + 3]);
    v0 = __fadd_rn(v0, blv[c + 0]); v1 = __fadd_rn(v1, blv[c + 1]);
    v2 = __fadd_rn(v2, blv[c + 2]); v3 = __fadd_rn(v3, blv[c + 3]);

    float4 ep = ((const float4*)eps)[d * 32 + lane];
    float4 wv = ((const float4*)w)[lane];
    float4 z;
    z.x = __fadd_rn(m0, __fmul_rn(ep.x, expf(__fmul_rn(0.5f, v0))));
    z.y = __fadd_rn(m1, __fmul_rn(ep.y, expf(__fmul_rn(0.5f, v1))));
    z.z = __fadd_rn(m2, __fmul_rn(ep.z, expf(__fmul_rn(0.5f, v2))));
    z.w = __fadd_rn(m3, __fmul_rn(ep.w, expf(__fmul_rn(0.5f, v3))));
    double dot = (double)z.x * wv.x + (double)z.y * wv.y
               + (double)z.z * wv.z + (double)z.w * wv.w;
    double wsq = (double)wv.x * wv.x + (double)wv.y * wv.y
               + (double)wv.z * wv.z + (double)wv.w * wv.w;
    #pragma unroll
    for (int o = 16; o > 0; o >>= 1) {
        dot += __shfl_xor_sync(0xffffffffu, dot, o);
        wsq += __shfl_xor_sync(0xffffffffu, wsq, o);
    }
    ((float4*)outMuLv)[d * 64 + lane]      = make_float4(m0, m1, m2, m3);
    ((float4*)outMuLv)[d * 64 + 32 + lane] = make_float4(v0, v1, v2, v3);
    ((float4*)g_z)[d * 32 + lane] = z;
    if (lane == 0) g_score[d] = (float)tanh(dot / sqrt(wsq));
}

// ---------------- per-graph top-k: bitonic sort of 1024 ----------------------
__device__ __forceinline__ bool later_than(float sa, int ia, float sb, int ib) {
    return (sa < sb) || (sa == sb && ia > ib);
}

__global__ __launch_bounds__(512) void k_topk() {
    __shared__ float ss[1024];
    __shared__ int   si[1024];
    int g = blockIdx.x;
    int t = threadIdx.x;
    int base = g * N_PER;
    ss[t] = g_score[base + t];             si[t] = t;
    ss[t + 512] = g_score[base + t + 512]; si[t + 512] = t + 512;
    __syncthreads();
    for (int k = 2; k <= 1024; k <<= 1) {
        for (int j = k >> 1; j > 0; j >>= 1) {
            for (int i = t; i < 1024; i += 512) {
                int l = i ^ j;
                if (l > i) {
                    bool up = ((i & k) == 0);
                    if (later_than(ss[i], si[i], ss[l], si[l]) == up) {
                        float ts = ss[i]; ss[i] = ss[l]; ss[l] = ts;
                        int ti = si[i]; si[i] = si[l]; si[l] = ti;
                    }
                }
            }
            __syncthreads();
        }
    }
    g_perm[g * K_PER + t] = base + si[t];
}

// ---------------- gather epilogue --------------------------------------------
__global__ __launch_bounds__(256) void k_output(float* __restrict__ out) {
    const int OFF_MU = N_OUT * LATENT;
    const int OFF_LV = 2 * N_OUT * LATENT;
    const int OFF_B  = 3 * N_OUT * LATENT;
    const int OFF_P  = OFF_B + N_OUT;
    int warp = (blockIdx.x * blockDim.x + threadIdx.x) >> 5;
    if (warp >= N_OUT) return;
    int lane = threadIdx.x & 31;
    int node = g_perm[warp];
    float sc = g_score[node];
    float4 z = ((const float4*)g_z)[node * 32 + lane];
    z.x = __fmul_rn(z.x, sc); z.y = __fmul_rn(z.y, sc);
    z.z = __fmul_rn(z.z, sc); z.w = __fmul_rn(z.w, sc);
    ((float4*)out)[warp * 32 + lane] = z;
    const float4* muv4 = (const float4*)g_buf1;
    ((float4*)(out + OFF_MU))[warp * 32 + lane] = muv4[node * 64 + lane];
    ((float4*)(out + OFF_LV))[warp * 32 + lane] = muv4[node * 64 + 32 + lane];
    if (lane == 0) {
        out[OFF_B + warp] = (float)(node >> 10);
        out[OFF_P + warp] = (float)node;
    }
}

// ---------------- launch ------------------------------------------------------
extern "C" void kernel_launch(void* const* d_in, const int* in_sizes, int n_in,
                              void* d_out, int out_size)
{
    const float* x_raw = (const float*)d_in[0];
    const float* pe    = (const float*)d_in[1];
    const void*  ei    = d_in[2];
    const float* eps   = (const float*)d_in[4];
    const float* W1    = (const float*)d_in[5];
    const float* b1    = (const float*)d_in[6];
    const float* Wmu   = (const float*)d_in[7];
    const float* bmu   = (const float*)d_in[8];
    const float* Wlv   = (const float*)d_in[9];
    const float* blv   = (const float*)d_in[10];
    const float* wpool = (const float*)d_in[11];
    float* out = (float*)d_out;

    float* buf0; cudaGetSymbolAddress((void**)&buf0, g_buf0);
    float* buf1; cudaGetSymbolAddress((void**)&buf1, g_buf1);

    static cudaStream_t s2 = 0;
    static cudaEvent_t evFork = 0, evJoin = 0;
    static int init_done = 0;
    if (!init_done) {
        init_done = 1;
        if (cudaStreamCreateWithFlags(&s2, cudaStreamNonBlocking) != cudaSuccess) s2 = 0;
        if (s2) {
            if (cudaEventCreateWithFlags(&evFork, cudaEventDisableTiming) != cudaSuccess ||
                cudaEventCreateWithFlags(&evJoin, cudaEventDisableTiming) != cudaSuccess)
                s2 = 0;
        }
    }

    dim3 gg(N_NODES / 128, 4);   // 128x64 tiles over N=256

    if (s2) {
        cudaEventRecord(evFork, 0);
        cudaStreamWaitEvent(s2, evFork, 0);
        k_zero<<<N_NODES / 256, 256, 0, s2>>>(ei);
        k_hist<<<N_EDGES / 256, 256, 0, s2>>>(ei);
        k_scan<<<1, 1024, 0, s2>>>();
        k_gemm<0><<<gg, 256>>>(x_raw, pe, W1, nullptr, buf0);   // main stream
        k_scatter<<<N_EDGES / 256, 256, 0, s2>>>(ei);
        k_sortrows<<<(N_NODES * 32) / 256, 256, 0, s2>>>();
        cudaEventRecord(evJoin, s2);
        cudaStreamWaitEvent(0, evJoin, 0);
    } else {
        k_zero<<<N_NODES / 256, 256>>>(ei);
        k_hist<<<N_EDGES / 256, 256>>>(ei);
        k_scan<<<1, 1024>>>();
        k_gemm<0><<<gg, 256>>>(x_raw, pe, W1, nullptr, buf0);
        k_scatter<<<N_EDGES / 256, 256>>>(ei);
        k_sortrows<<<(N_NODES * 32) / 256, 256>>>();
    }

    k_agg<<<(N_NODES * 64) / 256, 256>>>(buf0, buf1, b1, b1 + 128, 1);
    k_gemm<1><<<gg, 256>>>(buf1, nullptr, Wmu, Wlv, buf0);
    k_aggz<<<(N_NODES * 32) / 256, 256>>>(buf0, buf1, bmu, blv, eps, wpool);
    k_topk<<<NUM_G, 512>>>();
    k_output<<<(N_OUT * 32) / 256, 256>>>(out);
}

// round 10
// speedup vs baseline: 1.6094x; 1.0068x over previous
#include <cuda_runtime.h>
#include <cuda_bf16.h>
#include <math.h>

#define N_NODES   65536
#define N_EDGES   1048576
#define IN_DIM    192
#define PE_DIM    64
#define HIDDEN    256
#define LATENT    128
#define NUM_G     64
#define N_PER     1024
#define K_PER     512
#define N_OUT     (NUM_G * K_PER)          // 32768
#define MAX_DEG   128

typedef unsigned long long u64;

// ---------------- packed f32x2 helpers (sm_103a FFMA2 pipe) ------------------
__device__ __forceinline__ u64 ffma2(u64 a, u64 b, u64 c) {
    u64 d;
    asm("fma.rn.f32x2 %0, %1, %2, %3;" : "=l"(d) : "l"(a), "l"(b), "l"(c));
    return d;
}
__device__ __forceinline__ u64 fadd2(u64 a, u64 b) {
    u64 d;
    asm("add.rn.f32x2 %0, %1, %2;" : "=l"(d) : "l"(a), "l"(b));
    return d;
}
__device__ __forceinline__ u64 pack2(float lo, float hi) {
    u64 d;
    asm("mov.b64 %0, {%1, %2};" : "=l"(d) : "f"(lo), "f"(hi));
    return d;
}
__device__ __forceinline__ void unpack2(u64 v, float& lo, float& hi) {
    asm("mov.b64 {%0, %1}, %2;" : "=f"(lo), "=f"(hi) : "l"(v));
}

// ---------------- scratch (device globals; no allocation allowed) -----------
__device__ float g_buf0[N_NODES * 256];
__device__ float g_buf1[N_NODES * 256];
__device__ float g_z[N_NODES * LATENT];
__device__ float g_score[N_NODES];
__device__ float g_dinv[N_NODES];
__device__ int   g_cnt[N_NODES];
__device__ int   g_fill[N_NODES];
__device__ int   g_rowstart[N_NODES + 1];
__device__ int   g_colsrc[N_EDGES];
__device__ int   g_coledge[N_EDGES];
__device__ int   g_perm[N_OUT];
__device__ int   g_is64;

__device__ __forceinline__ int edge_at(const void* __restrict__ ei, int pos) {
    if (g_is64) return (int)((const long long*)ei)[pos];
    return ((const int*)ei)[pos];
}

// ---------------- CSR build ---------------------------------------------------
__global__ void k_zero(const void* __restrict__ ei) {
    int i = blockIdx.x * blockDim.x + threadIdx.x;
    if (i < N_NODES) { g_cnt[i] = 0; g_fill[i] = 0; }
    if (i == 0) {
        const unsigned long long* p = (const unsigned long long*)ei;
        int is64 = 1;
        for (int j = 0; j < 64; j++)
            if (p[j] > 65535ull) { is64 = 0; break; }
        g_is64 = is64;
    }
}

__global__ void k_hist(const void* __restrict__ ei) {
    int e = blockIdx.x * blockDim.x + threadIdx.x;
    if (e < N_EDGES) atomicAdd(&g_cnt[edge_at(ei, N_EDGES + e)], 1);
}

__global__ void k_scan() {
    __shared__ int sh[1024];
    int t = threadIdx.x;
    int base = t * 64;
    int s = 0;
    for (int j = 0; j < 64; j++) s += g_cnt[base + j];
    sh[t] = s;
    __syncthreads();
    int mine = s;
    for (int off = 1; off < 1024; off <<= 1) {
        int v = (t >= off) ? sh[t - off] : 0;
        __syncthreads();
        sh[t] += v;
        __syncthreads();
    }
    int run = sh[t] - mine;
    for (int j = 0; j < 64; j++) {
        int c = g_cnt[base + j];
        g_rowstart[base + j] = run;
        g_dinv[base + j] = (float)(1.0 / sqrt((double)(c + 1)));
        run += c;
    }
    if (t == 1023) g_rowstart[N_NODES] = sh[1023];
}

__global__ void k_scatter(const void* __restrict__ ei) {
    int e = blockIdx.x * blockDim.x + threadIdx.x;
    if (e < N_EDGES) {
        int s = edge_at(ei, e);
        int d = edge_at(ei, N_EDGES + e);
        int pos = g_rowstart[d] + atomicAdd(&g_fill[d], 1);
        g_colsrc[pos] = s;
        g_coledge[pos] = e;
    }
}

__global__ __launch_bounds__(256) void k_sortrows() {
    __shared__ int Es[8][MAX_DEG];
    __shared__ int Ss[8][MAX_DEG];
    int warp = (blockIdx.x * blockDim.x + threadIdx.x) >> 5;
    if (warp >= N_NODES) return;
    int lane = threadIdx.x & 31;
    int w = (threadIdx.x >> 5);
    int e0 = g_rowstart[warp], e1 = g_rowstart[warp + 1];
    int deg = e1 - e0;
    if (deg <= 1) return;
    if (deg > MAX_DEG) deg = MAX_DEG;
    for (int i = lane; i < deg; i += 32) {
        Es[w][i] = g_coledge[e0 + i];
        Ss[w][i] = g_colsrc[e0 + i];
    }
    __syncwarp();
    for (int i = lane; i < deg; i += 32) {
        int my_e = Es[w][i];
        int rank = 0;
        for (int j = 0; j < deg; j++) rank += (Es[w][j] < my_e);
        g_colsrc[e0 + rank] = Ss[w][i];
    }
}

// ---------------- GEMM (f32x2, double-buffered, 128x64 tile — proven) --------
template <int MODE>
__global__ __launch_bounds__(256) void k_gemm(
    const float* __restrict__ A0, const float* __restrict__ A1,
    const float* __restrict__ B0, const float* __restrict__ B1,
    float* __restrict__ C)
{
    __shared__ float As[2][16][130];
    __shared__ float Bs[2][16][64];
    int tid = threadIdx.x;
    int tx = tid & 15, ty = tid >> 4;
    int m0 = blockIdx.x * 128;
    int n0 = blockIdx.y * 64;

    int arow0 = tid >> 2;
    int aq0   = (tid & 3) * 4;
    int arow1 = (tid + 256) >> 2;
    int aq1   = aq0;
    int brow  = tid >> 4;
    int bq    = (tid & 15) * 4;

    u64 acc[4][4];
    #pragma unroll
    for (int i = 0; i < 4; i++)
        #pragma unroll
        for (int j = 0; j < 4; j++) acc[i][j] = 0ull;

    float4 va0, va1, vb;
    {
        int col0 = aq0, col1 = aq1;
        if (MODE == 0) {
            va0 = (col0 < IN_DIM) ? *(const float4*)&A0[(m0 + arow0) * IN_DIM + col0]
                                  : *(const float4*)&A1[(m0 + arow0) * PE_DIM + (col0 - IN_DIM)];
            va1 = (col1 < IN_DIM) ? *(const float4*)&A0[(m0 + arow1) * IN_DIM + col1]
                                  : *(const float4*)&A1[(m0 + arow1) * PE_DIM + (col1 - IN_DIM)];
            vb  = *(const float4*)&B0[brow * 256 + n0 + bq];
        } else {
            va0 = *(const float4*)&A0[(m0 + arow0) * 256 + col0];
            va1 = *(const float4*)&A0[(m0 + arow1) * 256 + col1];
            int col = n0 + bq;
            vb = (col < 128) ? *(const float4*)&B0[brow * 128 + col]
                             : *(const float4*)&B1[brow * 128 + (col - 128)];
        }
    }

    #pragma unroll 1
    for (int t = 0; t < 16; t++) {
        int cur = t & 1;
        As[cur][aq0 + 0][arow0] = va0.x; As[cur][aq0 + 1][arow0] = va0.y;
        As[cur][aq0 + 2][arow0] = va0.z; As[cur][aq0 + 3][arow0] = va0.w;
        As[cur][aq1 + 0][arow1] = va1.x; As[cur][aq1 + 1][arow1] = va1.y;
        As[cur][aq1 + 2][arow1] = va1.z; As[cur][aq1 + 3][arow1] = va1.w;
        *(float4*)&Bs[cur][brow][bq] = vb;
        __syncthreads();

        if (t < 15) {
            int k0 = (t + 1) * 16;
            int col0 = k0 + aq0, col1 = k0 + aq1;
            if (MODE == 0) {
                va0 = (col0 < IN_DIM) ? *(const float4*)&A0[(m0 + arow0) * IN_DIM + col0]
                                      : *(const float4*)&A1[(m0 + arow0) * PE_DIM + (col0 - IN_DIM)];
                va1 = (col1 < IN_DIM) ? *(const float4*)&A0[(m0 + arow1) * IN_DIM + col1]
                                      : *(const float4*)&A1[(m0 + arow1) * PE_DIM + (col1 - IN_DIM)];
                vb  = *(const float4*)&B0[(k0 + brow) * 256 + n0 + bq];
            } else {
                va0 = *(const float4*)&A0[(m0 + arow0) * 256 + col0];
                va1 = *(const float4*)&A0[(m0 + arow1) * 256 + col1];
                int col = n0 + bq;
                vb = (col < 128) ? *(const float4*)&B0[(k0 + brow) * 128 + col]
                                 : *(const float4*)&B1[(k0 + brow) * 128 + (col - 128)];
            }
        }

        u64 accT[4][4];
        #pragma unroll
        for (int i = 0; i < 4; i++)
            #pragma unroll
            for (int j = 0; j < 4; j++) accT[i][j] = 0ull;

        #pragma unroll
        for (int k = 0; k < 16; k++) {
            u64 ap[4];
            #pragma unroll
            for (int i = 0; i < 4; i++)
                ap[i] = *(const u64*)&As[cur][k][ty * 8 + 2 * i];
            float4 bv = *(const float4*)&Bs[cur][k][tx * 4];
            u64 bp[4] = { pack2(bv.x, bv.x), pack2(bv.y, bv.y),
                          pack2(bv.z, bv.z), pack2(bv.w, bv.w) };
            #pragma unroll
            for (int i = 0; i < 4; i++)
                #pragma unroll
                for (int j = 0; j < 4; j++)
                    accT[i][j] = ffma2(ap[i], bp[j], accT[i][j]);
        }
        #pragma unroll
        for (int i = 0; i < 4; i++)
            #pragma unroll
            for (int j = 0; j < 4; j++)
                acc[i][j] = fadd2(acc[i][j], accT[i][j]);
        __syncthreads();
    }
    #pragma unroll
    for (int i = 0; i < 4; i++) {
        float lo[4], hi[4];
        #pragma unroll
        for (int j = 0; j < 4; j++) unpack2(acc[i][j], lo[j], hi[j]);
        int r0 = m0 + ty * 8 + 2 * i;
        *(float4*)&C[r0 * 256 + n0 + tx * 4]       = make_float4(lo[0], lo[1], lo[2], lo[3]);
        *(float4*)&C[(r0 + 1) * 256 + n0 + tx * 4] = make_float4(hi[0], hi[1], hi[2], hi[3]);
    }
}

// ------ shared gather core: accumulate 4 features (lane*4) of one half ------
// Strict edge-order accumulation; 8/4/1 unroll for MLP.
__device__ __forceinline__ void agg_half(
    const float4* __restrict__ in4, int d, int lane, float dd,
    float& a0, float& a1, float& a2, float& a3)
{
    a0 = a1 = a2 = a3 = 0.f;
    int e0 = g_rowstart[d], e1 = g_rowstart[d + 1];
    int e = e0;
    for (; e + 7 < e1; e += 8) {
        int s[8]; float n[8]; float4 b[8];
        #pragma unroll
        for (int u = 0; u < 8; u++) s[u] = g_colsrc[e + u];
        #pragma unroll
        for (int u = 0; u < 8; u++) n[u] = __fmul_rn(g_dinv[s[u]], dd);
        #pragma unroll
        for (int u = 0; u < 8; u++) b[u] = in4[s[u] * 64 + lane];
        #pragma unroll
        for (int u = 0; u < 8; u++) {
            a0 = __fadd_rn(a0, __fmul_rn(n[u], b[u].x));
            a1 = __fadd_rn(a1, __fmul_rn(n[u], b[u].y));
            a2 = __fadd_rn(a2, __fmul_rn(n[u], b[u].z));
            a3 = __fadd_rn(a3, __fmul_rn(n[u], b[u].w));
        }
    }
    for (; e + 3 < e1; e += 4) {
        int s[4]; float n[4]; float4 b[4];
        #pragma unroll
        for (int u = 0; u < 4; u++) s[u] = g_colsrc[e + u];
        #pragma unroll
        for (int u = 0; u < 4; u++) n[u] = __fmul_rn(g_dinv[s[u]], dd);
        #pragma unroll
        for (int u = 0; u < 4; u++) b[u] = in4[s[u] * 64 + lane];
        #pragma unroll
        for (int u = 0; u < 4; u++) {
            a0 = __fadd_rn(a0, __fmul_rn(n[u], b[u].x));
            a1 = __fadd_rn(a1, __fmul_rn(n[u], b[u].y));
            a2 = __fadd_rn(a2, __fmul_rn(n[u], b[u].z));
            a3 = __fadd_rn(a3, __fmul_rn(n[u], b[u].w));
        }
    }
    for (; e < e1; e++) {
        int s0 = g_colsrc[e];
        float n0 = __fmul_rn(g_dinv[s0], dd);
        float4 b0 = in4[s0 * 64 + lane];
        a0 = __fadd_rn(a0, __fmul_rn(n0, b0.x));
        a1 = __fadd_rn(a1, __fmul_rn(n0, b0.y));
        a2 = __fadd_rn(a2, __fmul_rn(n0, b0.z));
        a3 = __fadd_rn(a3, __fmul_rn(n0, b0.w));
    }
    {   // self loop last (reference appends loops after edges)
        float ns = __fmul_rn(dd, dd);
        float4 b = in4[d * 64 + lane];
        a0 = __fadd_rn(a0, __fmul_rn(ns, b.x));
        a1 = __fadd_rn(a1, __fmul_rn(ns, b.y));
        a2 = __fadd_rn(a2, __fmul_rn(ns, b.z));
        a3 = __fadd_rn(a3, __fmul_rn(ns, b.w));
    }
}

// ---------------- conv1 aggregation: 2 warps per node + relu -----------------
__global__ __launch_bounds__(256) void k_agg(
    const float* __restrict__ in, float* __restrict__ out,
    const float* __restrict__ bias0, const float* __restrict__ bias1)
{
    int gw = (blockIdx.x * blockDim.x + threadIdx.x) >> 5;
    if (gw >= N_NODES * 2) return;
    int lane = threadIdx.x & 31;
    int d = gw >> 1;
    int half = gw & 1;
    const float4* in4 = (const float4*)in + half * 32;
    float dd = g_dinv[d];
    float a0, a1, a2, a3;
    agg_half(in4, d, lane, dd, a0, a1, a2, a3);
    const float* bias = half ? bias1 : bias0;
    int c = lane * 4;
    a0 = fmaxf(__fadd_rn(a0, bias[c + 0]), 0.f);
    a1 = fmaxf(__fadd_rn(a1, bias[c + 1]), 0.f);
    a2 = fmaxf(__fadd_rn(a2, bias[c + 2]), 0.f);
    a3 = fmaxf(__fadd_rn(a3, bias[c + 3]), 0.f);
    ((float4*)out + half * 32)[d * 64 + lane] = make_float4(a0, a1, a2, a3);
}

// ------ conv2 aggregation + z + score: 2 warps/node, smem lv exchange -------
__global__ __launch_bounds__(256) void k_agg2z(
    const float* __restrict__ in, float* __restrict__ outMuLv,
    const float* __restrict__ bmu, const float* __restrict__ blv,
    const float* __restrict__ eps, const float* __restrict__ w)
{
    __shared__ float slv[4][128];      // 4 nodes per block
    int gw = (blockIdx.x * blockDim.x + threadIdx.x) >> 5;
    int lane = threadIdx.x & 31;
    int wInB = (threadIdx.x >> 5);
    int nib = wInB >> 1;               // node index in block 0..3
    int d = gw >> 1;
    int half = gw & 1;
    const float4* in4 = (const float4*)in + half * 32;
    float dd = g_dinv[d];
    float a0, a1, a2, a3;
    agg_half(in4, d, lane, dd, a0, a1, a2, a3);
    const float* bias = half ? blv : bmu;
    int c = lane * 4;
    a0 = __fadd_rn(a0, bias[c + 0]);
    a1 = __fadd_rn(a1, bias[c + 1]);
    a2 = __fadd_rn(a2, bias[c + 2]);
    a3 = __fadd_rn(a3, bias[c + 3]);
    // store mu|lv for the output gather
    ((float4*)outMuLv + half * 32)[d * 64 + lane] = make_float4(a0, a1, a2, a3);
    // lv half publishes accumulators
    if (half) *(float4*)&slv[nib][c] = make_float4(a0, a1, a2, a3);
    __syncthreads();
    if (!half) {
        float4 lv = *(const float4*)&slv[nib][c];
        float4 ep = ((const float4*)eps)[d * 32 + lane];
        float4 wv = ((const float4*)w)[lane];
        float4 z;
        z.x = __fadd_rn(a0, __fmul_rn(ep.x, expf(__fmul_rn(0.5f, lv.x))));
        z.y = __fadd_rn(a1, __fmul_rn(ep.y, expf(__fmul_rn(0.5f, lv.y))));
        z.z = __fadd_rn(a2, __fmul_rn(ep.z, expf(__fmul_rn(0.5f, lv.z))));
        z.w = __fadd_rn(a3, __fmul_rn(ep.w, expf(__fmul_rn(0.5f, lv.w))));
        double dot = (double)z.x * wv.x + (double)z.y * wv.y
                   + (double)z.z * wv.z + (double)z.w * wv.w;
        double wsq = (double)wv.x * wv.x + (double)wv.y * wv.y
                   + (double)wv.z * wv.z + (double)wv.w * wv.w;
        #pragma unroll
        for (int o = 16; o > 0; o >>= 1) {
            dot += __shfl_xor_sync(0xffffffffu, dot, o);
            wsq += __shfl_xor_sync(0xffffffffu, wsq, o);
        }
        ((float4*)g_z)[d * 32 + lane] = z;
        if (lane == 0) g_score[d] = (float)tanh(dot / sqrt(wsq));
    }
}

// ---------------- per-graph top-k: bitonic sort of 1024 ----------------------
__device__ __forceinline__ bool later_than(float sa, int ia, float sb, int ib) {
    return (sa < sb) || (sa == sb && ia > ib);
}

__global__ __launch_bounds__(512) void k_topk() {
    __shared__ float ss[1024];
    __shared__ int   si[1024];
    int g = blockIdx.x;
    int t = threadIdx.x;
    int base = g * N_PER;
    ss[t] = g_score[base + t];             si[t] = t;
    ss[t + 512] = g_score[base + t + 512]; si[t + 512] = t + 512;
    __syncthreads();
    for (int k = 2; k <= 1024; k <<= 1) {
        for (int j = k >> 1; j > 0; j >>= 1) {
            for (int i = t; i < 1024; i += 512) {
                int l = i ^ j;
                if (l > i) {
                    bool up = ((i & k) == 0);
                    if (later_than(ss[i], si[i], ss[l], si[l]) == up) {
                        float ts = ss[i]; ss[i] = ss[l]; ss[l] = ts;
                        int ti = si[i]; si[i] = si[l]; si[l] = ti;
                    }
                }
            }
            __syncthreads();
        }
    }
    g_perm[g * K_PER + t] = base + si[t];
}

// ---------------- gather epilogue --------------------------------------------
__global__ __launch_bounds__(256) void k_output(float* __restrict__ out) {
    const int OFF_MU = N_OUT * LATENT;
    const int OFF_LV = 2 * N_OUT * LATENT;
    const int OFF_B  = 3 * N_OUT * LATENT;
    const int OFF_P  = OFF_B + N_OUT;
    int warp = (blockIdx.x * blockDim.x + threadIdx.x) >> 5;
    if (warp >= N_OUT) return;
    int lane = threadIdx.x & 31;
    int node = g_perm[warp];
    float sc = g_score[node];
    float4 z = ((const float4*)g_z)[node * 32 + lane];
    z.x = __fmul_rn(z.x, sc); z.y = __fmul_rn(z.y, sc);
    z.z = __fmul_rn(z.z, sc); z.w = __fmul_rn(z.w, sc);
    ((float4*)out)[warp * 32 + lane] = z;
    const float4* muv4 = (const float4*)g_buf1;
    ((float4*)(out + OFF_MU))[warp * 32 + lane] = muv4[node * 64 + lane];
    ((float4*)(out + OFF_LV))[warp * 32 + lane] = muv4[node * 64 + 32 + lane];
    if (lane == 0) {
        out[OFF_B + warp] = (float)(node >> 10);
        out[OFF_P + warp] = (float)node;
    }
}

// ---------------- launch ------------------------------------------------------
extern "C" void kernel_launch(void* const* d_in, const int* in_sizes, int n_in,
                              void* d_out, int out_size)
{
    const float* x_raw = (const float*)d_in[0];
    const float* pe    = (const float*)d_in[1];
    const void*  ei    = d_in[2];
    const float* eps   = (const float*)d_in[4];
    const float* W1    = (const float*)d_in[5];
    const float* b1    = (const float*)d_in[6];
    const float* Wmu   = (const float*)d_in[7];
    const float* bmu   = (const float*)d_in[8];
    const float* Wlv   = (const float*)d_in[9];
    const float* blv   = (const float*)d_in[10];
    const float* wpool = (const float*)d_in[11];
    float* out = (float*)d_out;

    float* buf0; cudaGetSymbolAddress((void**)&buf0, g_buf0);
    float* buf1; cudaGetSymbolAddress((void**)&buf1, g_buf1);

    static cudaStream_t s2 = 0;
    static cudaEvent_t evFork = 0, evJoin = 0;
    static int init_done = 0;
    if (!init_done) {
        init_done = 1;
        if (cudaStreamCreateWithFlags(&s2, cudaStreamNonBlocking) != cudaSuccess) s2 = 0;
        if (s2) {
            if (cudaEventCreateWithFlags(&evFork, cudaEventDisableTiming) != cudaSuccess ||
                cudaEventCreateWithFlags(&evJoin, cudaEventDisableTiming) != cudaSuccess)
                s2 = 0;
        }
    }

    dim3 gg(N_NODES / 128, 4);

    if (s2) {
        cudaEventRecord(evFork, 0);
        cudaStreamWaitEvent(s2, evFork, 0);
        k_zero<<<N_NODES / 256, 256, 0, s2>>>(ei);
        k_hist<<<N_EDGES / 256, 256, 0, s2>>>(ei);
        k_scan<<<1, 1024, 0, s2>>>();
        k_gemm<0><<<gg, 256>>>(x_raw, pe, W1, nullptr, buf0);   // main stream
        k_scatter<<<N_EDGES / 256, 256, 0, s2>>>(ei);
        k_sortrows<<<(N_NODES * 32) / 256, 256, 0, s2>>>();
        cudaEventRecord(evJoin, s2);
        cudaStreamWaitEvent(0, evJoin, 0);
    } else {
        k_zero<<<N_NODES / 256, 256>>>(ei);
        k_hist<<<N_EDGES / 256, 256>>>(ei);
        k_scan<<<1, 1024>>>();
        k_gemm<0><<<gg, 256>>>(x_raw, pe, W1, nullptr, buf0);
        k_scatter<<<N_EDGES / 256, 256>>>(ei);
        k_sortrows<<<(N_NODES * 32) / 256, 256>>>();
    }

    k_agg<<<(N_NODES * 64) / 256, 256>>>(buf0, buf1, b1, b1 + 128);
    k_gemm<1><<<gg, 256>>>(buf1, nullptr, Wmu, Wlv, buf0);
    k_agg2z<<<(N_NODES * 64) / 256, 256>>>(buf0, buf1, bmu, blv, eps, wpool);
    k_topk<<<NUM_G, 512>>>();
    k_output<<<(N_OUT * 32) / 256, 256>>>(out);
}